// round 1
// baseline (speedup 1.0000x reference)
#include <cuda_runtime.h>

#define BB 8
#define CC 256
#define HH 96
#define WW 96
#define HS 192
#define WS 192
#define OC 32
#define GG 4
#define CG 64   // CC/GG

// Offset field scratch: [B][G][HS][WS] x float2 (x-offset, y-offset) interleaved
__device__ float g_off[BB * GG * HS * WS * 2];

// ---------------------------------------------------------------------------
// Kernel 1: 1x1 conv (32 outputs over 256 channels) + tanh + pixel_shuffle(2)
// One thread = one low-res pixel, 32 accumulators, weights transposed in smem.
// ---------------------------------------------------------------------------
__global__ __launch_bounds__(256) void conv_offset_kernel(
    const float* __restrict__ x, const float* __restrict__ w,
    const float* __restrict__ bias)
{
    __shared__ __align__(16) float wT[CC * OC];  // wT[c*32 + o]
    int tid = threadIdx.x;
    #pragma unroll
    for (int k = 0; k < (CC * OC) / 256; ++k) {
        int flat = tid + k * 256;
        int c = flat >> 5, o = flat & 31;
        wT[flat] = w[o * CC + c];
    }
    __syncthreads();

    int p   = blockIdx.x * 256 + tid;       // 0 .. B*H*W-1 (73728)
    int b   = p / (HH * WW);
    int rem = p - b * (HH * WW);
    int h   = rem / WW;
    int wp  = rem - h * WW;

    float acc[OC];
    #pragma unroll
    for (int o = 0; o < OC; ++o) acc[o] = bias[o];

    const float* xp = x + (b * CC) * (HH * WW) + h * WW + wp;
    #pragma unroll 4
    for (int c = 0; c < CC; ++c) {
        float xv = __ldg(xp + c * (HH * WW));
        const float4* wrow = (const float4*)(wT + c * OC);
        #pragma unroll
        for (int q = 0; q < OC / 4; ++q) {
            float4 wv = wrow[q];
            acc[q * 4 + 0] += xv * wv.x;
            acc[q * 4 + 1] += xv * wv.y;
            acc[q * 4 + 2] += xv * wv.z;
            acc[q * 4 + 3] += xv * wv.w;
        }
    }

    // pixel_shuffle(2) + tanh + scatter into interleaved (x,y) offset field
    #pragma unroll
    for (int o = 0; o < OC; ++o) {
        int co   = o >> 2;          // 0..7  channel after shuffle
        int i    = (o >> 1) & 1;    // row sub-position
        int j    = o & 1;           // col sub-position
        int gidx = co >> 1;         // group 0..3
        int k    = co & 1;          // 0 = x-offset, 1 = y-offset
        int hs = 2 * h + i, ws = 2 * wp + j;
        float v = tanhf(acc[o]);
        g_off[((((b * GG + gidx) * HS + hs) * WS + ws) << 1) + k] = v;
    }
}

// ---------------------------------------------------------------------------
// Kernel 2: bilinear border grid_sample. One thread = one (b,g,hs,ws) pixel,
// index math hoisted, loops over the 64 channels of its group.
// ---------------------------------------------------------------------------
__global__ __launch_bounds__(256) void gather_kernel(
    const float* __restrict__ x, float* __restrict__ out)
{
    const int tiles = (HS * WS) / 256;      // 144
    int bg   = blockIdx.x / tiles;          // 0..31 = b*4 + gidx
    int tile = blockIdx.x - bg * tiles;
    int pix  = tile * 256 + threadIdx.x;
    int hs   = pix / WS;
    int ws   = pix - hs * WS;
    int b    = bg >> 2;
    int gidx = bg & 3;

    float2 off = ((const float2*)g_off)[(bg * HS + hs) * WS + ws];

    // grid math collapsed: gx = (base_x + 0.125*off + 1)*48 - 0.5
    float gx = (float)ws * 0.5f - 0.25f + 6.0f * off.x;
    float gy = (float)hs * 0.5f - 0.25f + 6.0f * off.y;
    gx = fminf(fmaxf(gx, 0.0f), (float)(WW - 1));
    gy = fminf(fmaxf(gy, 0.0f), (float)(HH - 1));

    int x0 = (int)gx;   // floor (gx >= 0)
    int y0 = (int)gy;
    float wx = gx - (float)x0;
    float wy = gy - (float)y0;
    int dx = (x0 < WW - 1) ? 1  : 0;
    int dy = (y0 < HH - 1) ? WW : 0;
    int i00 = y0 * WW + x0;

    float w00 = (1.0f - wx) * (1.0f - wy);
    float w01 = wx * (1.0f - wy);
    float w10 = (1.0f - wx) * wy;
    float w11 = wx * wy;

    const float* xp = x + (b * CC + gidx * CG) * (HH * WW);
    float*       op = out + ((b * CC + gidx * CG) * HS + hs) * WS + ws;

    #pragma unroll 4
    for (int c = 0; c < CG; ++c) {
        float v00 = __ldg(xp + i00);
        float v01 = __ldg(xp + i00 + dx);
        float v10 = __ldg(xp + i00 + dy);
        float v11 = __ldg(xp + i00 + dy + dx);
        *op = v00 * w00 + v01 * w01 + v10 * w10 + v11 * w11;
        xp += HH * WW;
        op += HS * WS;
    }
}

extern "C" void kernel_launch(void* const* d_in, const int* in_sizes, int n_in,
                              void* d_out, int out_size) {
    const float* x    = (const float*)d_in[0];
    const float* w    = (const float*)d_in[1];
    const float* bias = (const float*)d_in[2];
    float* out        = (float*)d_out;

    conv_offset_kernel<<<(BB * HH * WW) / 256, 256>>>(x, w, bias);
    gather_kernel<<<BB * GG * ((HS * WS) / 256), 256>>>(x, out);
}